// round 1
// baseline (speedup 1.0000x reference)
#include <cuda_runtime.h>
#include <cuda_bf16.h>

#define NN_MAX 50000
#define NE_MAX 800000
#define HID 128

// scratch (device globals — no allocation allowed)
__device__ int   g_deg[NN_MAX];
__device__ int   g_off[NN_MAX + 1];
__device__ int   g_cursor[NN_MAX];
__device__ int   g_adj[NE_MAX];
__device__ float g_dinv[NN_MAX];
__device__ float g_ht[NN_MAX * HID];
__device__ float g_act[NN_MAX * HID];
__device__ int   g_part[256];

// ---------------- CSR build ----------------

__global__ void k_zero_deg(int* deg, int n) {
    int i = blockIdx.x * blockDim.x + threadIdx.x;
    if (i < n) deg[i] = 0;
}

__global__ void k_count(const int* __restrict__ dst, int* deg, int E) {
    int e = blockIdx.x * blockDim.x + threadIdx.x;
    if (e < E) atomicAdd(&deg[dst[e]], 1);
}

// per-block exclusive scan of deg chunk -> off, block sums -> part
__global__ void k_scan_block(const int* __restrict__ deg, int* off, int* part, int n) {
    __shared__ int s[256];
    int tid = threadIdx.x;
    int gid = blockIdx.x * 256 + tid;
    int v = (gid < n) ? deg[gid] : 0;
    s[tid] = v;
    __syncthreads();
    #pragma unroll
    for (int d = 1; d < 256; d <<= 1) {
        int t = 0;
        if (tid >= d) t = s[tid - d];
        __syncthreads();
        s[tid] += t;
        __syncthreads();
    }
    if (gid < n) off[gid] = s[tid] - v;   // exclusive
    if (tid == 255) part[blockIdx.x] = s[255];
}

__global__ void k_scan_partials(int* part, int nb) {
    if (threadIdx.x == 0 && blockIdx.x == 0) {
        int run = 0;
        for (int b = 0; b < nb; ++b) { int v = part[b]; part[b] = run; run += v; }
    }
}

__global__ void k_finalize(int* off, const int* __restrict__ part, int* cursor,
                           const int* __restrict__ deg, float* dinv, int n, int E) {
    int gid = blockIdx.x * 256 + threadIdx.x;
    if (gid < n) {
        int o = off[gid] + part[blockIdx.x];
        off[gid] = o;
        cursor[gid] = o;
        dinv[gid] = rsqrtf((float)(deg[gid] + 1));  // +1 self loop
    }
    if (gid == 0) off[n] = E;
}

__global__ void k_fill_adj(const int* __restrict__ src, const int* __restrict__ dst,
                           int* cursor, int* adj, int E) {
    int e = blockIdx.x * blockDim.x + threadIdx.x;
    if (e < E) {
        int d = dst[e];
        int pos = atomicAdd(&cursor[d], 1);
        adj[pos] = src[e];
    }
}

// ---------------- GEMM: out[i,:] = (X[i,:] @ W) * dinv[i] ----------------
// X: [n,128], W: [128,128] row-major. Block = 256 threads, 64 rows/block.
// smem: Xs 64x128 (32KB) + Ws 32x128 chunk (16KB) = 48KB static.

__global__ __launch_bounds__(256) void k_gemm(const float* __restrict__ X,
                                              const float* __restrict__ W,
                                              const float* __restrict__ dinv,
                                              float* __restrict__ out, int n) {
    __shared__ float Xs[64 * 128];
    __shared__ float Ws[32 * 128];
    float4* Xs4 = reinterpret_cast<float4*>(Xs);
    float4* Ws4 = reinterpret_cast<float4*>(Ws);
    const float4* Xg = reinterpret_cast<const float4*>(X);
    const float4* Wg = reinterpret_cast<const float4*>(W);

    int tid = threadIdx.x;
    int row0 = blockIdx.x * 64;

    // load X tile (guarded)
    #pragma unroll
    for (int t = 0; t < 8; ++t) {
        int idx = tid + t * 256;       // 0..2047 float4s
        int r = idx >> 5;              // row in tile
        int c4 = idx & 31;
        int grow = row0 + r;
        float4 v = make_float4(0.f, 0.f, 0.f, 0.f);
        if (grow < n) v = Xg[grow * 32 + c4];
        Xs4[idx] = v;
    }

    float4 acc[8];
    #pragma unroll
    for (int r = 0; r < 8; ++r) acc[r] = make_float4(0.f, 0.f, 0.f, 0.f);

    int tc = tid & 31;          // col group: columns tc*4..tc*4+3
    int tr = (tid >> 5) * 8;    // row base within tile

    #pragma unroll
    for (int kt = 0; kt < 4; ++kt) {
        __syncthreads();
        // load W chunk rows [kt*32, kt*32+32)
        #pragma unroll
        for (int t = 0; t < 4; ++t) {
            int idx = tid + t * 256;   // 0..1023
            Ws4[idx] = Wg[kt * 1024 + idx];
        }
        __syncthreads();
        #pragma unroll
        for (int k4 = 0; k4 < 8; ++k4) {
            float4 w0 = Ws4[(k4 * 4 + 0) * 32 + tc];
            float4 w1 = Ws4[(k4 * 4 + 1) * 32 + tc];
            float4 w2 = Ws4[(k4 * 4 + 2) * 32 + tc];
            float4 w3 = Ws4[(k4 * 4 + 3) * 32 + tc];
            #pragma unroll
            for (int r = 0; r < 8; ++r) {
                float4 xv = Xs4[(tr + r) * 32 + kt * 8 + k4];
                acc[r].x += xv.x * w0.x; acc[r].y += xv.x * w0.y;
                acc[r].z += xv.x * w0.z; acc[r].w += xv.x * w0.w;
                acc[r].x += xv.y * w1.x; acc[r].y += xv.y * w1.y;
                acc[r].z += xv.y * w1.z; acc[r].w += xv.y * w1.w;
                acc[r].x += xv.z * w2.x; acc[r].y += xv.z * w2.y;
                acc[r].z += xv.z * w2.z; acc[r].w += xv.z * w2.w;
                acc[r].x += xv.w * w3.x; acc[r].y += xv.w * w3.y;
                acc[r].z += xv.w * w3.z; acc[r].w += xv.w * w3.w;
            }
        }
    }

    float4* Og = reinterpret_cast<float4*>(out);
    #pragma unroll
    for (int r = 0; r < 8; ++r) {
        int grow = row0 + tr + r;
        if (grow < n) {
            float s = dinv[grow];
            float4 v = acc[r];
            v.x *= s; v.y *= s; v.z *= s; v.w *= s;
            Og[grow * 32 + tc] = v;
        }
    }
}

// ---------------- Aggregation + bias + LayerNorm + ReLU ----------------
// One 128-thread block per node. ht rows are pre-scaled by dinv[src].

__device__ __forceinline__ float block_reduce_128(float v, float* sh) {
    #pragma unroll
    for (int o = 16; o; o >>= 1) v += __shfl_xor_sync(0xffffffffu, v, o);
    int w = threadIdx.x >> 5;
    if ((threadIdx.x & 31) == 0) sh[w] = v;
    __syncthreads();
    float r = sh[0] + sh[1] + sh[2] + sh[3];
    __syncthreads();
    return r;
}

__global__ void k_agg_ln(const float* __restrict__ ht, const int* __restrict__ adj,
                         const int* __restrict__ off, const float* __restrict__ dinv,
                         const float* __restrict__ bias, const float* __restrict__ gamma,
                         const float* __restrict__ beta, float* __restrict__ out, int n) {
    __shared__ float sh[4];
    int i = blockIdx.x;
    if (i >= n) return;
    int c = threadIdx.x;

    float a = ht[i * HID + c];     // self loop term (already * dinv[i] ... no, * dinv of self as src)
    int s = off[i], e = off[i + 1];
    for (int p = s; p < e; ++p) {
        int j = adj[p];            // broadcast load
        a += ht[j * HID + c];
    }
    float v = a * dinv[i] + bias[c];

    float mu = block_reduce_128(v, sh) * (1.0f / 128.0f);
    float d = v - mu;
    float var = block_reduce_128(d * d, sh) * (1.0f / 128.0f);
    float r = d * rsqrtf(var + 1e-5f) * gamma[c] + beta[c];
    out[i * HID + c] = fmaxf(r, 0.0f);
}

// ---------------- launch ----------------

extern "C" void kernel_launch(void* const* d_in, const int* in_sizes, int n_in,
                              void* d_out, int out_size) {
    const float* x     = (const float*)d_in[0];
    const int*   edges = (const int*)d_in[1];
    const float* W1    = (const float*)d_in[2];
    const float* b1    = (const float*)d_in[3];
    const float* g1    = (const float*)d_in[4];
    const float* be1   = (const float*)d_in[5];
    const float* W2    = (const float*)d_in[6];
    const float* b2    = (const float*)d_in[7];
    const float* g2    = (const float*)d_in[8];
    const float* be2   = (const float*)d_in[9];
    float* out = (float*)d_out;

    int n = in_sizes[0] / HID;
    int E = in_sizes[1] / 2;
    const int* src = edges;
    const int* dst = edges + E;

    int *deg, *off, *cursor, *adj, *part;
    float *dinv, *ht, *act;
    cudaGetSymbolAddress((void**)&deg, g_deg);
    cudaGetSymbolAddress((void**)&off, g_off);
    cudaGetSymbolAddress((void**)&cursor, g_cursor);
    cudaGetSymbolAddress((void**)&adj, g_adj);
    cudaGetSymbolAddress((void**)&part, g_part);
    cudaGetSymbolAddress((void**)&dinv, g_dinv);
    cudaGetSymbolAddress((void**)&ht, g_ht);
    cudaGetSymbolAddress((void**)&act, g_act);

    int nbN = (n + 255) / 256;
    int nbE = (E + 255) / 256;
    int nbG = (n + 63) / 64;

    k_zero_deg<<<nbN, 256>>>(deg, n);
    k_count<<<nbE, 256>>>(dst, deg, E);
    k_scan_block<<<nbN, 256>>>(deg, off, part, n);
    k_scan_partials<<<1, 32>>>(part, nbN);
    k_finalize<<<nbN, 256>>>(off, part, cursor, deg, dinv, n, E);
    k_fill_adj<<<nbE, 256>>>(src, dst, cursor, adj, E);

    // layer 1
    k_gemm<<<nbG, 256>>>(x, W1, dinv, ht, n);
    k_agg_ln<<<n, 128>>>(ht, adj, off, dinv, b1, g1, be1, act, n);
    // layer 2
    k_gemm<<<nbG, 256>>>(act, W2, dinv, ht, n);
    k_agg_ln<<<n, 128>>>(ht, adj, off, dinv, b2, g2, be2, out, n);
}